// round 16
// baseline (speedup 1.0000x reference)
#include <cuda_runtime.h>
#include <cuda_fp16.h>
#include <cstdint>

// Problem constants
#define NN      64
#define TT      512
#define BB      64
#define PP      32
#define KDIM    4096        // N*N
#define NCOLS   512         // T

// ---------------------------------------------------------------------------
// Device scratch (static — allocation-free per harness rules)
// g_w layout: g_w[t*4096 + i*64 + j]
// Operands stored TILED fp16: tile = [128 rows x 32 k] = 8 KB contiguous,
// SW64-swizzled; consecutive kc tiles are contiguous, so a 64-k stage is
// fetched with 2 bulk copies of 16 KB.
// ---------------------------------------------------------------------------
__device__ float g_w[TT * KDIM];
__device__ __half g_f16_t[(size_t)KDIM * KDIM];        // 33.5 MB tiled
__device__ __half w2t_f16_t[(size_t)NCOLS * KDIM];     // 4 MB tiled
__device__ float g_Zp[4][BB * NN];                     // gather partials

// ---------------------------------------------------------------------------
// PTX helpers (baseline sm_90-level PTX, valid on plain sm_103 target)
// ---------------------------------------------------------------------------
__device__ __forceinline__ uint32_t smem_u32(const void* p) {
    uint32_t a;
    asm("{ .reg .u64 t; cvta.to.shared.u64 t, %1; cvt.u32.u64 %0, t; }"
        : "=r"(a) : "l"(p));
    return a;
}

__device__ __forceinline__ void cp_bulk(uint32_t dst, const void* src,
                                        uint32_t bytes, uint32_t mbar) {
    asm volatile(
        "cp.async.bulk.shared::cluster.global.mbarrier::complete_tx::bytes "
        "[%0], [%1], %2, [%3];"
        :: "r"(dst), "l"(src), "r"(bytes), "r"(mbar) : "memory");
}

__device__ __forceinline__ void mbar_init(uint32_t mbar, uint32_t cnt) {
    asm volatile("mbarrier.init.shared.b64 [%0], %1;" :: "r"(mbar), "r"(cnt)
                 : "memory");
}

__device__ __forceinline__ void mbar_expect_tx(uint32_t mbar, uint32_t bytes) {
    asm volatile("mbarrier.arrive.expect_tx.shared.b64 _, [%0], %1;"
                 :: "r"(mbar), "r"(bytes) : "memory");
}

__device__ __forceinline__ void mbar_wait(uint32_t mbar, uint32_t parity) {
    asm volatile(
        "{\n\t"
        ".reg .pred P1;\n\t"
        "WAIT_LOOP_%=:\n\t"
        "mbarrier.try_wait.parity.acquire.cta.shared::cta.b64 P1, [%0], %1, 0x989680;\n\t"
        "@P1 bra.uni WAIT_DONE_%=;\n\t"
        "bra.uni WAIT_LOOP_%=;\n\t"
        "WAIT_DONE_%=:\n\t"
        "}"
        :: "r"(mbar), "r"(parity) : "memory");
}

#define LDSM4(r, addr)                                                         \
    asm volatile("ldmatrix.sync.aligned.m8n8.x4.shared.b16 "                   \
                 "{%0,%1,%2,%3}, [%4];"                                        \
                 : "=r"((r)[0]), "=r"((r)[1]), "=r"((r)[2]), "=r"((r)[3])      \
                 : "r"(addr))

#define MMA16816F16(c, a, b0, b1)                                              \
    asm volatile("mma.sync.aligned.m16n8k16.row.col.f32.f16.f16.f32 "          \
                 "{%0,%1,%2,%3},{%4,%5,%6,%7},{%8,%9},{%0,%1,%2,%3};"          \
                 : "+f"((c)[0]), "+f"((c)[1]), "+f"((c)[2]), "+f"((c)[3])      \
                 : "r"((a)[0]), "r"((a)[1]), "r"((a)[2]), "r"((a)[3]),         \
                   "r"(b0), "r"(b1))

// SW64 swizzle for 64-byte rows (conflict-free ldmatrix, proven)
__device__ __forceinline__ uint32_t swz64(uint32_t off) {
    return off ^ ((off >> 3) & 0x30);
}

__device__ __forceinline__ uint32_t pk_h2(float x, float y) {
    return ((uint32_t)__half_as_ushort(__float2half_rn(y)) << 16) |
           __half_as_ushort(__float2half_rn(x));
}
__device__ __forceinline__ uint4 pack8_f16(const float4& u, const float4& v) {
    uint4 h;
    h.x = pk_h2(u.x, u.y); h.y = pk_h2(u.z, u.w);
    h.z = pk_h2(v.x, v.y); h.w = pk_h2(v.z, v.w);
    return h;
}

// ---------------------------------------------------------------------------
// Kernel 0a: convert g (fp32, row-major) to fp16 tiled+swizzled.
// ---------------------------------------------------------------------------
__global__ __launch_bounds__(256, 4)
void split_g_kernel(const float* __restrict__ g) {
    const int kc = blockIdx.x;
    const int bm = blockIdx.y;
    const int tid = threadIdx.x;
    const size_t tbase = (size_t)(bm * 128 + kc) * 8192;
#pragma unroll
    for (int j = 0; j < 2; j++) {
        const int id  = tid + j * 256;
        const int row = id >> 2;
        const int c16 = id & 3;
        const float* p = g + (size_t)(bm * 128 + row) * KDIM + kc * 32 + c16 * 8;
        const float4 v0 = *(const float4*)p;
        const float4 v1 = *(const float4*)(p + 4);
        const uint4 h = pack8_f16(v0, v1);
        const uint32_t off = swz64((uint32_t)(row * 64 + c16 * 16));
        *(uint4*)((char*)g_f16_t + tbase + off) = h;
    }
}

// ---------------------------------------------------------------------------
// Kernel 0b: weights [K=4096, T=512] -> (w^2)^T tiled fp16.
// ---------------------------------------------------------------------------
__global__ __launch_bounds__(256, 2)
void split_w_kernel(const float* __restrict__ w) {
    __shared__ float tile[128][33];   // [t_local][k_local]
    const int kc = blockIdx.x;
    const int bn = blockIdx.y;
    const int tid = threadIdx.x;

#pragma unroll
    for (int j = 0; j < 16; j++) {
        const int id = tid + j * 256;
        const int kl = id >> 7;
        const int tl = id & 127;
        const float v = w[(size_t)(kc * 32 + kl) * NCOLS + bn * 128 + tl];
        tile[tl][kl] = v * v;
    }
    __syncthreads();

    const size_t tbase = (size_t)(bn * 128 + kc) * 8192;
#pragma unroll
    for (int j = 0; j < 2; j++) {
        const int id = tid + j * 256;
        const int r  = id >> 2;
        const int c16 = id & 3;
        float4 u, v;
        u.x = tile[r][c16 * 8 + 0]; u.y = tile[r][c16 * 8 + 1];
        u.z = tile[r][c16 * 8 + 2]; u.w = tile[r][c16 * 8 + 3];
        v.x = tile[r][c16 * 8 + 4]; v.y = tile[r][c16 * 8 + 5];
        v.z = tile[r][c16 * 8 + 6]; v.w = tile[r][c16 * 8 + 7];
        const uint4 h = pack8_f16(u, v);
        const uint32_t off = swz64((uint32_t)(r * 64 + c16 * 16));
        *(uint4*)((char*)w2t_f16_t + tbase + off) = h;
    }
}

// ---------------------------------------------------------------------------
// Kernel 1: F = g @ weights^2, single-pass fp16 HMMA, TMA loads, fused
// row-softmax epilogue with smem-staged coalesced g_w stores.
//   Grid (4, 32). CTA tile 128x128 over K=4096. 256 threads = 8 warps
//   (2M x 4N), warp tile 64x32.
//   Stage = 64 k (two contiguous 8KB tiles per operand, 32 KB total),
//   4-slot TMA ring (128 KB), 64 stages.
// ---------------------------------------------------------------------------
#define ATILE   8192
#define STAGE_B (4 * ATILE)                // 32 KB: A(kc)|A(kc+1)|B(kc)|B(kc+1)
#define NSLOT   4
#define SMEM_T  (NSLOT * STAGE_B)          // 128 KB
#define KSTAGES (KDIM / 64)                // 64

__global__ __launch_bounds__(256, 1)
void mma_gemm_kernel(float* __restrict__ F) {
    extern __shared__ char smem[];
    __shared__ uint64_t mbars[NSLOT];
    const uint32_t sb = smem_u32(smem);
    const uint32_t mb0 = smem_u32(&mbars[0]);
    const int tid  = threadIdx.x;
    const int lane = tid & 31;
    const int wid  = tid >> 5;
    const int bn = blockIdx.x;             // 0..3
    const int bm = blockIdx.y;             // 0..31
    const int wm = wid >> 2;               // 0..1 -> row offset wm*64
    const int wn = wid & 3;                // 0..3 -> col offset wn*32

    const char* Ag = (const char*)g_f16_t   + (size_t)(bm * 128) * 8192;
    const char* Bg = (const char*)w2t_f16_t + (size_t)(bn * 128) * 8192;

    if (tid == 0) {
#pragma unroll
        for (int i = 0; i < NSLOT; i++) mbar_init(mb0 + i * 8, 1);
    }
    __syncthreads();

    auto issue = [&](int s) {
        const int slot = s & (NSLOT - 1);
        const uint32_t mb  = mb0 + slot * 8;
        const uint32_t dst = sb + slot * STAGE_B;
        mbar_expect_tx(mb, STAGE_B);
        const size_t to = (size_t)s * 16384;    // two 8KB tiles per operand
        cp_bulk(dst,         Ag + to, 16384u, mb);
        cp_bulk(dst + 16384, Bg + to, 16384u, mb);
    };

    if (tid == 0) { issue(0); issue(1); issue(2); }

    float c[4][4][4];
#pragma unroll
    for (int mt = 0; mt < 4; mt++)
#pragma unroll
        for (int nt = 0; nt < 4; nt++)
#pragma unroll
            for (int q = 0; q < 4; q++) c[mt][nt][q] = 0.f;

    const int rA    = lane & 15;
    const int kHalf = (lane >> 4) << 4;

    for (int s = 0; s < KSTAGES; s++) {
        const int slot = s & (NSLOT - 1);
        if (tid == 0 && s + NSLOT - 1 < KSTAGES) issue(s + NSLOT - 1);

        mbar_wait(mb0 + slot * 8, (s >> 2) & 1);

        const uint32_t ab = sb + slot * STAGE_B;
        const uint32_t bb = ab + 16384;

#pragma unroll
        for (int kk = 0; kk < 4; kk++) {          // 4 x K=16 per 64-chunk
            const uint32_t tof = (uint32_t)(kk >> 1) * 8192;  // which 8KB tile
            const int kb = (kk & 1) * 32 + kHalf;
            uint32_t ahr[4][4];
#pragma unroll
            for (int mt = 0; mt < 4; mt++) {
                const int row = wm * 64 + mt * 16 + rA;
                const uint32_t off = swz64((uint32_t)(row * 64 + kb));
                LDSM4(ahr[mt], ab + tof + off);
            }
#pragma unroll
            for (int gg = 0; gg < 2; gg++) {
                uint32_t bhr[4];
                const int row = wn * 32 + gg * 16 + rA;
                const uint32_t off = swz64((uint32_t)(row * 64 + kb));
                LDSM4(bhr, bb + tof + off);
#pragma unroll
                for (int mt = 0; mt < 4; mt++)
#pragma unroll
                    for (int h = 0; h < 2; h++)
                        MMA16816F16(c[mt][gg * 2 + h], ahr[mt], bhr[h], bhr[h + 2]);
            }
        }
        __syncthreads();     // all warps done reading slot before reuse
    }

    // ---- epilogue 1: write raw F (row-major [4096, 512]) ----
    const int r_lo = lane >> 2;
    const int c_lo = (lane & 3) * 2;
#pragma unroll
    for (int mt = 0; mt < 4; mt++) {
        const int row0 = bm * 128 + wm * 64 + mt * 16 + r_lo;
#pragma unroll
        for (int nt = 0; nt < 4; nt++) {
            const int col = bn * 128 + wn * 32 + nt * 8 + c_lo;
            float2 v0 = make_float2(c[mt][nt][0], c[mt][nt][1]);
            float2 v1 = make_float2(c[mt][nt][2], c[mt][nt][3]);
            *(float2*)(F + (size_t)row0 * NCOLS + col)       = v0;
            *(float2*)(F + (size_t)(row0 + 8) * NCOLS + col) = v1;
        }
    }

    // ---- epilogue 2: fused softmax over the warp's 64 rows, per column ----
    float mA[4], mB[4], sA[4], sB[4];
#pragma unroll
    for (int nt = 0; nt < 4; nt++) {
        float ma = -3.402823466e+38f, mb = ma;
#pragma unroll
        for (int mt = 0; mt < 4; mt++) {
            ma = fmaxf(ma, fmaxf(c[mt][nt][0], c[mt][nt][2]));
            mb = fmaxf(mb, fmaxf(c[mt][nt][1], c[mt][nt][3]));
        }
        ma = fmaxf(ma, __shfl_xor_sync(0xffffffffu, ma, 4));
        ma = fmaxf(ma, __shfl_xor_sync(0xffffffffu, ma, 8));
        ma = fmaxf(ma, __shfl_xor_sync(0xffffffffu, ma, 16));
        mb = fmaxf(mb, __shfl_xor_sync(0xffffffffu, mb, 4));
        mb = fmaxf(mb, __shfl_xor_sync(0xffffffffu, mb, 8));
        mb = fmaxf(mb, __shfl_xor_sync(0xffffffffu, mb, 16));
        mA[nt] = ma; mB[nt] = mb;
    }
#pragma unroll
    for (int nt = 0; nt < 4; nt++) {
        float sa = 0.f, sbv = 0.f;
#pragma unroll
        for (int mt = 0; mt < 4; mt++) {
            c[mt][nt][0] = __expf(c[mt][nt][0] - mA[nt]);
            c[mt][nt][2] = __expf(c[mt][nt][2] - mA[nt]);
            c[mt][nt][1] = __expf(c[mt][nt][1] - mB[nt]);
            c[mt][nt][3] = __expf(c[mt][nt][3] - mB[nt]);
            sa  += c[mt][nt][0] + c[mt][nt][2];
            sbv += c[mt][nt][1] + c[mt][nt][3];
        }
        sa  += __shfl_xor_sync(0xffffffffu, sa, 4);
        sa  += __shfl_xor_sync(0xffffffffu, sa, 8);
        sa  += __shfl_xor_sync(0xffffffffu, sa, 16);
        sbv += __shfl_xor_sync(0xffffffffu, sbv, 4);
        sbv += __shfl_xor_sync(0xffffffffu, sbv, 8);
        sbv += __shfl_xor_sync(0xffffffffu, sbv, 16);
        sA[nt] = 1.f / sa; sB[nt] = 1.f / sbv;
    }

    // ---- epilogue 3: stage w through (now idle) pipeline smem, then store
    //      coalesced. Warp layout sw[tl*72 + j], stride 72 -> <=2-way banks.
    float* sw = (float*)smem + wid * 2304;   // 2304 floats = 9216 B per warp
#pragma unroll
    for (int nt = 0; nt < 4; nt++) {
        const int tl = nt * 8 + c_lo;         // even 0..30
#pragma unroll
        for (int mt = 0; mt < 4; mt++) {
            const int j0 = mt * 16 + r_lo;
            sw[tl * 72 + j0]           = c[mt][nt][0] * sA[nt];
            sw[tl * 72 + j0 + 8]       = c[mt][nt][2] * sA[nt];
            sw[(tl + 1) * 72 + j0]     = c[mt][nt][1] * sB[nt];
            sw[(tl + 1) * 72 + j0 + 8] = c[mt][nt][3] * sB[nt];
        }
    }
    __syncwarp();
    // w: g_w[t*4096 + i*64 + j], i = 2*bm + wm (one i-group per warp)
    const int ibase = (2 * bm + wm) * 64;
    const int tbase = bn * 128 + wn * 32;
#pragma unroll
    for (int tl = 0; tl < 32; tl++) {
        const float v0 = sw[tl * 72 + lane];
        const float v1 = sw[tl * 72 + 32 + lane];
        float* dst = g_w + (size_t)(tbase + tl) * KDIM + ibase;
        dst[lane]      = v0;
        dst[32 + lane] = v1;
    }
}

// ---------------------------------------------------------------------------
// Kernel 3: gather. Grid (B, 4), 256 threads; block z handles the 8 p's
// [z*8, z*8+8). Warp wid owns one p. Per (p, n-pair): lanes 0-15 cover
// n via float4 over m (coalesced), lanes 16-31 cover n+1; 4-deep shfl.
// Partials tree-reduced in smem (deterministic) -> g_Zp[z].
// ---------------------------------------------------------------------------
__global__ __launch_bounds__(256, 4)
void gather_kernel(const float* __restrict__ x,
                   const int* __restrict__ xi) {
    __shared__ float xs[PP * 68];       // xs[p*68 + m] = x[b, m, p]
    __shared__ int   ti[PP];
    __shared__ float part[8 * NN];      // part[pl*64 + n]
    __shared__ float ps2[4 * NN];

    const int b    = blockIdx.x;
    const int z    = blockIdx.y;
    const int tid  = threadIdx.x;
    const int lane = tid & 31;
    const int wid  = tid >> 5;          // 0..7

    if (tid < PP) ti[tid] = xi[b * PP + tid];
#pragma unroll
    for (int j = 0; j < 2; j++) {
        // x[b] is 2048 floats = 512 float4; thread stages two.
        const int id = tid + j * 256;
        const float4 v = ((const float4*)(x + (size_t)b * NN * PP))[id];
        const int m  = id >> 3;         // 0..63
        const int p0 = (id & 7) * 4;    // 0,4,...,28
        xs[(p0 + 0) * 68 + m] = v.x;
        xs[(p0 + 1) * 68 + m] = v.y;
        xs[(p0 + 2) * 68 + m] = v.z;
        xs[(p0 + 3) * 68 + m] = v.w;
    }
    __syncthreads();

    const int m4 = lane & 15;           // float4 index over m
    const int nh = lane >> 4;           // 0/1: which n of the pair
    {
        const int p = z * 8 + wid;
        const int t = ti[p];
        const float* wrow = g_w + (size_t)t * KDIM;
        const float4 xp = *(const float4*)&xs[p * 68 + m4 * 4];
#pragma unroll 4
        for (int nn = 0; nn < 32; nn++) {
            const int n = nn * 2 + nh;
            const float4 wv = *(const float4*)(wrow + n * 64 + m4 * 4);
            float v = wv.x * xp.x + wv.y * xp.y + wv.z * xp.z + wv.w * xp.w;
            v += __shfl_xor_sync(0xffffffffu, v, 8);
            v += __shfl_xor_sync(0xffffffffu, v, 4);
            v += __shfl_xor_sync(0xffffffffu, v, 2);
            v += __shfl_xor_sync(0xffffffffu, v, 1);
            if (m4 == 0) part[wid * 64 + n] = v;
        }
    }
    __syncthreads();

    // stage-2: thread (q = tid/64 in 0..3, n = tid%64) sums 2 p's
    {
        const int n = tid & 63;
        const int q = tid >> 6;
        ps2[q * 64 + n] = part[(q * 2 + 0) * 64 + n]
                        + part[(q * 2 + 1) * 64 + n];
    }
    __syncthreads();

    if (tid < NN) {
        g_Zp[z][b * NN + tid] = ps2[tid] + ps2[64 + tid]
                              + ps2[128 + tid] + ps2[192 + tid];
    }
}

// ---------------------------------------------------------------------------
// Kernel 3b: Z = sum of the 4 gather partials (deterministic)
// ---------------------------------------------------------------------------
__global__ __launch_bounds__(256, 4)
void zfinal_kernel(float* __restrict__ Z) {
    const int i = blockIdx.x * 256 + threadIdx.x;   // 0..4095
    Z[i] = (g_Zp[0][i] + g_Zp[1][i]) + (g_Zp[2][i] + g_Zp[3][i]);
}

// ---------------------------------------------------------------------------
// Launch. Inputs: x [B,N,P] f32, x_i [B,P] i32, g [4096,4096] f32,
//                 weights [4096,512] f32.  Output: Z (4096 f32) then F.
// ---------------------------------------------------------------------------
extern "C" void kernel_launch(void* const* d_in, const int* in_sizes, int n_in,
                              void* d_out, int out_size) {
    const float* x   = (const float*)d_in[0];
    const int*   xi  = (const int*)d_in[1];
    const float* g   = (const float*)d_in[2];
    const float* wts = (const float*)d_in[3];

    float* Z = (float*)d_out;
    float* F = (float*)d_out + NN * NN;

    cudaFuncSetAttribute(mma_gemm_kernel,
                         cudaFuncAttributeMaxDynamicSharedMemorySize, SMEM_T);

    split_g_kernel<<<dim3(KDIM / 32, KDIM / 128), 256>>>(g);
    split_w_kernel<<<dim3(KDIM / 32, NCOLS / 128), 256>>>(wts);

    mma_gemm_kernel<<<dim3(NCOLS / 128, KDIM / 128), 256, SMEM_T>>>(F);

    gather_kernel<<<dim3(BB, 4), 256>>>(x, xi);
    zfinal_kernel<<<(BB * NN) / 256, 256>>>(Z);
}

// round 17
// speedup vs baseline: 1.0263x; 1.0263x over previous
#include <cuda_runtime.h>
#include <cuda_fp16.h>
#include <cstdint>

// Problem constants
#define NN      64
#define TT      512
#define BB      64
#define PP      32
#define KDIM    4096        // N*N
#define NCOLS   512         // T

// ---------------------------------------------------------------------------
// Device scratch (static — allocation-free per harness rules)
// g_w layout: g_w[t*4096 + i*64 + j]
// Operands stored TILED fp16: tile = [128 rows x 32 k] = 8 KB contiguous,
// SW64-swizzled (swizzle permutes only within 64B rows, so any 64-row half
// of a tile is a contiguous 4 KB block).
// ---------------------------------------------------------------------------
__device__ float g_w[TT * KDIM];
__device__ __half g_f16_t[(size_t)KDIM * KDIM];        // 33.5 MB tiled
__device__ __half w2t_f16_t[(size_t)NCOLS * KDIM];     // 4 MB tiled
__device__ float g_Zp[4][BB * NN];                     // gather partials

// ---------------------------------------------------------------------------
// PTX helpers (baseline sm_90-level PTX, valid on plain sm_103 target)
// ---------------------------------------------------------------------------
__device__ __forceinline__ uint32_t smem_u32(const void* p) {
    uint32_t a;
    asm("{ .reg .u64 t; cvta.to.shared.u64 t, %1; cvt.u32.u64 %0, t; }"
        : "=r"(a) : "l"(p));
    return a;
}

__device__ __forceinline__ void cp_bulk(uint32_t dst, const void* src,
                                        uint32_t bytes, uint32_t mbar) {
    asm volatile(
        "cp.async.bulk.shared::cluster.global.mbarrier::complete_tx::bytes "
        "[%0], [%1], %2, [%3];"
        :: "r"(dst), "l"(src), "r"(bytes), "r"(mbar) : "memory");
}

__device__ __forceinline__ void mbar_init(uint32_t mbar, uint32_t cnt) {
    asm volatile("mbarrier.init.shared.b64 [%0], %1;" :: "r"(mbar), "r"(cnt)
                 : "memory");
}

__device__ __forceinline__ void mbar_expect_tx(uint32_t mbar, uint32_t bytes) {
    asm volatile("mbarrier.arrive.expect_tx.shared.b64 _, [%0], %1;"
                 :: "r"(mbar), "r"(bytes) : "memory");
}

__device__ __forceinline__ void mbar_wait(uint32_t mbar, uint32_t parity) {
    asm volatile(
        "{\n\t"
        ".reg .pred P1;\n\t"
        "WAIT_LOOP_%=:\n\t"
        "mbarrier.try_wait.parity.acquire.cta.shared::cta.b64 P1, [%0], %1, 0x989680;\n\t"
        "@P1 bra.uni WAIT_DONE_%=;\n\t"
        "bra.uni WAIT_LOOP_%=;\n\t"
        "WAIT_DONE_%=:\n\t"
        "}"
        :: "r"(mbar), "r"(parity) : "memory");
}

#define LDSM4(r, addr)                                                         \
    asm volatile("ldmatrix.sync.aligned.m8n8.x4.shared.b16 "                   \
                 "{%0,%1,%2,%3}, [%4];"                                        \
                 : "=r"((r)[0]), "=r"((r)[1]), "=r"((r)[2]), "=r"((r)[3])      \
                 : "r"(addr))

#define MMA16816F16(c, a, b0, b1)                                              \
    asm volatile("mma.sync.aligned.m16n8k16.row.col.f32.f16.f16.f32 "          \
                 "{%0,%1,%2,%3},{%4,%5,%6,%7},{%8,%9},{%0,%1,%2,%3};"          \
                 : "+f"((c)[0]), "+f"((c)[1]), "+f"((c)[2]), "+f"((c)[3])      \
                 : "r"((a)[0]), "r"((a)[1]), "r"((a)[2]), "r"((a)[3]),         \
                   "r"(b0), "r"(b1))

// SW64 swizzle for 64-byte rows (conflict-free ldmatrix, proven)
__device__ __forceinline__ uint32_t swz64(uint32_t off) {
    return off ^ ((off >> 3) & 0x30);
}

__device__ __forceinline__ uint32_t pk_h2(float x, float y) {
    return ((uint32_t)__half_as_ushort(__float2half_rn(y)) << 16) |
           __half_as_ushort(__float2half_rn(x));
}
__device__ __forceinline__ uint4 pack8_f16(const float4& u, const float4& v) {
    uint4 h;
    h.x = pk_h2(u.x, u.y); h.y = pk_h2(u.z, u.w);
    h.z = pk_h2(v.x, v.y); h.w = pk_h2(v.z, v.w);
    return h;
}

// ---------------------------------------------------------------------------
// Kernel 0a: convert g (fp32, row-major) to fp16 tiled+swizzled.
// ---------------------------------------------------------------------------
__global__ __launch_bounds__(256, 4)
void split_g_kernel(const float* __restrict__ g) {
    const int kc = blockIdx.x;
    const int bm = blockIdx.y;
    const int tid = threadIdx.x;
    const size_t tbase = (size_t)(bm * 128 + kc) * 8192;
#pragma unroll
    for (int j = 0; j < 2; j++) {
        const int id  = tid + j * 256;
        const int row = id >> 2;
        const int c16 = id & 3;
        const float* p = g + (size_t)(bm * 128 + row) * KDIM + kc * 32 + c16 * 8;
        const float4 v0 = *(const float4*)p;
        const float4 v1 = *(const float4*)(p + 4);
        const uint4 h = pack8_f16(v0, v1);
        const uint32_t off = swz64((uint32_t)(row * 64 + c16 * 16));
        *(uint4*)((char*)g_f16_t + tbase + off) = h;
    }
}

// ---------------------------------------------------------------------------
// Kernel 0b: weights [K=4096, T=512] -> (w^2)^T tiled fp16.
// ---------------------------------------------------------------------------
__global__ __launch_bounds__(256, 2)
void split_w_kernel(const float* __restrict__ w) {
    __shared__ float tile[128][33];   // [t_local][k_local]
    const int kc = blockIdx.x;
    const int bn = blockIdx.y;
    const int tid = threadIdx.x;

#pragma unroll
    for (int j = 0; j < 16; j++) {
        const int id = tid + j * 256;
        const int kl = id >> 7;
        const int tl = id & 127;
        const float v = w[(size_t)(kc * 32 + kl) * NCOLS + bn * 128 + tl];
        tile[tl][kl] = v * v;
    }
    __syncthreads();

    const size_t tbase = (size_t)(bn * 128 + kc) * 8192;
#pragma unroll
    for (int j = 0; j < 2; j++) {
        const int id = tid + j * 256;
        const int r  = id >> 2;
        const int c16 = id & 3;
        float4 u, v;
        u.x = tile[r][c16 * 8 + 0]; u.y = tile[r][c16 * 8 + 1];
        u.z = tile[r][c16 * 8 + 2]; u.w = tile[r][c16 * 8 + 3];
        v.x = tile[r][c16 * 8 + 4]; v.y = tile[r][c16 * 8 + 5];
        v.z = tile[r][c16 * 8 + 6]; v.w = tile[r][c16 * 8 + 7];
        const uint4 h = pack8_f16(u, v);
        const uint32_t off = swz64((uint32_t)(r * 64 + c16 * 16));
        *(uint4*)((char*)w2t_f16_t + tbase + off) = h;
    }
}

// ---------------------------------------------------------------------------
// Kernel 1: F = g @ weights^2, single-pass fp16 HMMA, TMA loads, fused
// row-softmax epilogue with smem-staged coalesced g_w stores.
//   Grid (8, 32): CTA tile 128 x 64 over K=4096 -> 256 CTAs, 2 CTAs/SM,
//   4 warps/SMSP (occupancy experiment vs R16's 128 CTAs @ 1/SM).
//   8 warps (2M x 4N), warp tile 64x16.
//   Stage = 64 k: A = two contiguous 8KB tiles (16 KB bulk copy);
//   B = the CTA's 64-row half of two tiles (two 4 KB bulk copies).
//   4-slot TMA ring, 96 KB smem.
// ---------------------------------------------------------------------------
#define ASTAGE  16384                      // A: [128 x 64k] fp16
#define BSTAGE  8192                       // B: [64 x 64k] fp16
#define STAGE_B (ASTAGE + BSTAGE)          // 24 KB
#define NSLOT   4
#define SMEM_T  (NSLOT * STAGE_B)          // 96 KB
#define KSTAGES (KDIM / 64)                // 64

__global__ __launch_bounds__(256, 2)
void mma_gemm_kernel(float* __restrict__ F) {
    extern __shared__ char smem[];
    __shared__ uint64_t mbars[NSLOT];
    const uint32_t sb = smem_u32(smem);
    const uint32_t mb0 = smem_u32(&mbars[0]);
    const int tid  = threadIdx.x;
    const int lane = tid & 31;
    const int wid  = tid >> 5;
    const int bn = blockIdx.x;             // 0..7 (64-col tiles of T)
    const int bm = blockIdx.y;             // 0..31
    const int wm = wid >> 2;               // 0..1 -> row offset wm*64
    const int wn = wid & 3;                // 0..3 -> col offset wn*16

    const char* Ag = (const char*)g_f16_t + (size_t)(bm * 128) * 8192;
    // B: row-block (bn>>1) of w2t tiles; this CTA uses the (bn&1) 64-row half
    const char* Bg = (const char*)w2t_f16_t + (size_t)(bn >> 1) * (128 * 8192);
    const uint32_t halfoff = (uint32_t)(bn & 1) * 4096;

    if (tid == 0) {
#pragma unroll
        for (int i = 0; i < NSLOT; i++) mbar_init(mb0 + i * 8, 1);
    }
    __syncthreads();

    auto issue = [&](int s) {
        const int slot = s & (NSLOT - 1);
        const uint32_t mb  = mb0 + slot * 8;
        const uint32_t dst = sb + slot * STAGE_B;
        mbar_expect_tx(mb, STAGE_B);
        const size_t to = (size_t)s * 16384;    // two 8KB tiles per stage
        cp_bulk(dst, Ag + to, 16384u, mb);
        cp_bulk(dst + ASTAGE,        Bg + to + halfoff,        4096u, mb);
        cp_bulk(dst + ASTAGE + 4096, Bg + to + 8192 + halfoff, 4096u, mb);
    };

    if (tid == 0) { issue(0); issue(1); issue(2); }

    float c[4][2][4];
#pragma unroll
    for (int mt = 0; mt < 4; mt++)
#pragma unroll
        for (int nt = 0; nt < 2; nt++)
#pragma unroll
            for (int q = 0; q < 4; q++) c[mt][nt][q] = 0.f;

    const int rA    = lane & 15;
    const int kHalf = (lane >> 4) << 4;

    for (int s = 0; s < KSTAGES; s++) {
        const int slot = s & (NSLOT - 1);
        if (tid == 0 && s + NSLOT - 1 < KSTAGES) issue(s + NSLOT - 1);

        mbar_wait(mb0 + slot * 8, (s >> 2) & 1);

        const uint32_t ab = sb + slot * STAGE_B;
        const uint32_t bb = ab + ASTAGE;

#pragma unroll
        for (int kk = 0; kk < 4; kk++) {          // 4 x K=16 per 64-chunk
            const uint32_t atof = (uint32_t)(kk >> 1) * 8192;
            const uint32_t btof = (uint32_t)(kk >> 1) * 4096;
            const int kb = (kk & 1) * 32 + kHalf;
            uint32_t ahr[4][4];
#pragma unroll
            for (int mt = 0; mt < 4; mt++) {
                const int row = wm * 64 + mt * 16 + rA;
                const uint32_t off = swz64((uint32_t)(row * 64 + kb));
                LDSM4(ahr[mt], ab + atof + off);
            }
            uint32_t bhr[4];
            {
                const int row = wn * 16 + rA;     // local n row 0..63
                const uint32_t off = swz64((uint32_t)(row * 64 + kb));
                LDSM4(bhr, bb + btof + off);
            }
#pragma unroll
            for (int mt = 0; mt < 4; mt++)
#pragma unroll
                for (int h = 0; h < 2; h++)
                    MMA16816F16(c[mt][h], ahr[mt], bhr[h], bhr[h + 2]);
        }
        __syncthreads();     // all warps done reading slot before reuse
    }

    // ---- epilogue 1: write raw F (row-major [4096, 512]) ----
    const int r_lo = lane >> 2;
    const int c_lo = (lane & 3) * 2;
#pragma unroll
    for (int mt = 0; mt < 4; mt++) {
        const int row0 = bm * 128 + wm * 64 + mt * 16 + r_lo;
#pragma unroll
        for (int nt = 0; nt < 2; nt++) {
            const int col = bn * 64 + wn * 16 + nt * 8 + c_lo;
            float2 v0 = make_float2(c[mt][nt][0], c[mt][nt][1]);
            float2 v1 = make_float2(c[mt][nt][2], c[mt][nt][3]);
            *(float2*)(F + (size_t)row0 * NCOLS + col)       = v0;
            *(float2*)(F + (size_t)(row0 + 8) * NCOLS + col) = v1;
        }
    }

    // ---- epilogue 2: fused softmax over the warp's 64 rows, per column ----
    float mA[2], mB[2], sA[2], sB[2];
#pragma unroll
    for (int nt = 0; nt < 2; nt++) {
        float ma = -3.402823466e+38f, mb = ma;
#pragma unroll
        for (int mt = 0; mt < 4; mt++) {
            ma = fmaxf(ma, fmaxf(c[mt][nt][0], c[mt][nt][2]));
            mb = fmaxf(mb, fmaxf(c[mt][nt][1], c[mt][nt][3]));
        }
        ma = fmaxf(ma, __shfl_xor_sync(0xffffffffu, ma, 4));
        ma = fmaxf(ma, __shfl_xor_sync(0xffffffffu, ma, 8));
        ma = fmaxf(ma, __shfl_xor_sync(0xffffffffu, ma, 16));
        mb = fmaxf(mb, __shfl_xor_sync(0xffffffffu, mb, 4));
        mb = fmaxf(mb, __shfl_xor_sync(0xffffffffu, mb, 8));
        mb = fmaxf(mb, __shfl_xor_sync(0xffffffffu, mb, 16));
        mA[nt] = ma; mB[nt] = mb;
    }
#pragma unroll
    for (int nt = 0; nt < 2; nt++) {
        float sa = 0.f, sbv = 0.f;
#pragma unroll
        for (int mt = 0; mt < 4; mt++) {
            c[mt][nt][0] = __expf(c[mt][nt][0] - mA[nt]);
            c[mt][nt][2] = __expf(c[mt][nt][2] - mA[nt]);
            c[mt][nt][1] = __expf(c[mt][nt][1] - mB[nt]);
            c[mt][nt][3] = __expf(c[mt][nt][3] - mB[nt]);
            sa  += c[mt][nt][0] + c[mt][nt][2];
            sbv += c[mt][nt][1] + c[mt][nt][3];
        }
        sa  += __shfl_xor_sync(0xffffffffu, sa, 4);
        sa  += __shfl_xor_sync(0xffffffffu, sa, 8);
        sa  += __shfl_xor_sync(0xffffffffu, sa, 16);
        sbv += __shfl_xor_sync(0xffffffffu, sbv, 4);
        sbv += __shfl_xor_sync(0xffffffffu, sbv, 8);
        sbv += __shfl_xor_sync(0xffffffffu, sbv, 16);
        sA[nt] = 1.f / sa; sB[nt] = 1.f / sbv;
    }

    // ---- epilogue 3: stage w through pipeline smem, then store coalesced.
    //      Warp layout sw[tl*72 + j], tl = local t (0..15), stride 72.
    float* sw = (float*)smem + wid * 1152;   // 1152 floats = 4608 B per warp
#pragma unroll
    for (int nt = 0; nt < 2; nt++) {
        const int tl = nt * 8 + c_lo;         // even 0..14
#pragma unroll
        for (int mt = 0; mt < 4; mt++) {
            const int j0 = mt * 16 + r_lo;
            sw[tl * 72 + j0]           = c[mt][nt][0] * sA[nt];
            sw[tl * 72 + j0 + 8]       = c[mt][nt][2] * sA[nt];
            sw[(tl + 1) * 72 + j0]     = c[mt][nt][1] * sB[nt];
            sw[(tl + 1) * 72 + j0 + 8] = c[mt][nt][3] * sB[nt];
        }
    }
    __syncwarp();
    // w: g_w[t*4096 + i*64 + j], i = 2*bm + wm (one i-group per warp)
    const int ibase = (2 * bm + wm) * 64;
    const int tbase = bn * 64 + wn * 16;
#pragma unroll
    for (int tl = 0; tl < 16; tl++) {
        const float v0 = sw[tl * 72 + lane];
        const float v1 = sw[tl * 72 + 32 + lane];
        float* dst = g_w + (size_t)(tbase + tl) * KDIM + ibase;
        dst[lane]      = v0;
        dst[32 + lane] = v1;
    }
}

// ---------------------------------------------------------------------------
// Kernel 3: gather. Grid (B, 4), 256 threads; block z handles the 8 p's
// [z*8, z*8+8). Warp wid owns one p. (R16 version, frozen.)
// ---------------------------------------------------------------------------
__global__ __launch_bounds__(256, 4)
void gather_kernel(const float* __restrict__ x,
                   const int* __restrict__ xi) {
    __shared__ float xs[PP * 68];       // xs[p*68 + m] = x[b, m, p]
    __shared__ int   ti[PP];
    __shared__ float part[8 * NN];      // part[pl*64 + n]
    __shared__ float ps2[4 * NN];

    const int b    = blockIdx.x;
    const int z    = blockIdx.y;
    const int tid  = threadIdx.x;
    const int lane = tid & 31;
    const int wid  = tid >> 5;          // 0..7

    if (tid < PP) ti[tid] = xi[b * PP + tid];
#pragma unroll
    for (int j = 0; j < 2; j++) {
        const int id = tid + j * 256;
        const float4 v = ((const float4*)(x + (size_t)b * NN * PP))[id];
        const int m  = id >> 3;         // 0..63
        const int p0 = (id & 7) * 4;    // 0,4,...,28
        xs[(p0 + 0) * 68 + m] = v.x;
        xs[(p0 + 1) * 68 + m] = v.y;
        xs[(p0 + 2) * 68 + m] = v.z;
        xs[(p0 + 3) * 68 + m] = v.w;
    }
    __syncthreads();

    const int m4 = lane & 15;           // float4 index over m
    const int nh = lane >> 4;           // 0/1: which n of the pair
    {
        const int p = z * 8 + wid;
        const int t = ti[p];
        const float* wrow = g_w + (size_t)t * KDIM;
        const float4 xp = *(const float4*)&xs[p * 68 + m4 * 4];
#pragma unroll 4
        for (int nn = 0; nn < 32; nn++) {
            const int n = nn * 2 + nh;
            const float4 wv = *(const float4*)(wrow + n * 64 + m4 * 4);
            float v = wv.x * xp.x + wv.y * xp.y + wv.z * xp.z + wv.w * xp.w;
            v += __shfl_xor_sync(0xffffffffu, v, 8);
            v += __shfl_xor_sync(0xffffffffu, v, 4);
            v += __shfl_xor_sync(0xffffffffu, v, 2);
            v += __shfl_xor_sync(0xffffffffu, v, 1);
            if (m4 == 0) part[wid * 64 + n] = v;
        }
    }
    __syncthreads();

    {
        const int n = tid & 63;
        const int q = tid >> 6;
        ps2[q * 64 + n] = part[(q * 2 + 0) * 64 + n]
                        + part[(q * 2 + 1) * 64 + n];
    }
    __syncthreads();

    if (tid < NN) {
        g_Zp[z][b * NN + tid] = ps2[tid] + ps2[64 + tid]
                              + ps2[128 + tid] + ps2[192 + tid];
    }
}

// ---------------------------------------------------------------------------
// Kernel 3b: Z = sum of the 4 gather partials (deterministic)
// ---------------------------------------------------------------------------
__global__ __launch_bounds__(256, 4)
void zfinal_kernel(float* __restrict__ Z) {
    const int i = blockIdx.x * 256 + threadIdx.x;   // 0..4095
    Z[i] = (g_Zp[0][i] + g_Zp[1][i]) + (g_Zp[2][i] + g_Zp[3][i]);
}

// ---------------------------------------------------------------------------
// Launch. Inputs: x [B,N,P] f32, x_i [B,P] i32, g [4096,4096] f32,
//                 weights [4096,512] f32.  Output: Z (4096 f32) then F.
// ---------------------------------------------------------------------------
extern "C" void kernel_launch(void* const* d_in, const int* in_sizes, int n_in,
                              void* d_out, int out_size) {
    const float* x   = (const float*)d_in[0];
    const int*   xi  = (const int*)d_in[1];
    const float* g   = (const float*)d_in[2];
    const float* wts = (const float*)d_in[3];

    float* Z = (float*)d_out;
    float* F = (float*)d_out + NN * NN;

    cudaFuncSetAttribute(mma_gemm_kernel,
                         cudaFuncAttributeMaxDynamicSharedMemorySize, SMEM_T);

    split_g_kernel<<<dim3(KDIM / 32, KDIM / 128), 256>>>(g);
    split_w_kernel<<<dim3(KDIM / 32, NCOLS / 128), 256>>>(wts);

    mma_gemm_kernel<<<dim3(NCOLS / 64, KDIM / 128), 256, SMEM_T>>>(F);

    gather_kernel<<<dim3(BB, 4), 256>>>(x, xi);
    zfinal_kernel<<<(BB * NN) / 256, 256>>>(Z);
}